// round 15
// baseline (speedup 1.0000x reference)
#include <cuda_runtime.h>

#define TT 1024
#define EE 256
#define DD 64
#define BB 2
#define JCH 64        // keys per chunk (attn)
#define PROWS 8       // rows per proj block (grid = 256)
#define PCH 32        // e-rows per proj weight chunk
#define NPCH (EE / PCH)

// Scratch (device globals: no allocation allowed in kernel_launch)
__device__ float g_qpb[BB * TT * DD];   // qp + b1, row-major [row][d]
__device__ float g_kpT[BB * DD * TT];   // kp transposed   [b][d][t]
__device__ float g_v  [BB * TT * DD];   // v, row-major    [row][dv]
// split-K partials
__device__ float g_po[2][BB * TT * DD]; // unnormalized o
__device__ float g_pm[2][BB * TT];      // running max
__device__ float g_pl[2][BB * TT];      // denominator

__device__ __forceinline__ void cp16(float* dst, const float* src) {
    unsigned d = (unsigned)__cvta_generic_to_shared(dst);
    asm volatile("cp.async.cg.shared.global [%0], [%1], 16;" :: "r"(d), "l"(src));
}
__device__ __forceinline__ void cp_commit() { asm volatile("cp.async.commit_group;"); }
template <int N>
__device__ __forceinline__ void cp_wait() { asm volatile("cp.async.wait_group %0;" :: "n"(N)); }

// Warp-wide float max via integer redux.sync (f32 redux doesn't exist).
__device__ __forceinline__ float warp_max_f32(float x) {
    unsigned ix = __float_as_uint(x);
    ix = (ix & 0x80000000u) ? ~ix : (ix | 0x80000000u);
    unsigned r = __reduce_max_sync(0xffffffffu, ix);
    r = (r & 0x80000000u) ? (r & 0x7fffffffu) : ~r;
    return __uint_as_float(r);
}

// ---------------------------------------------------------------------------
// Kernel 1 (v4c): projections — unchanged from R13 (best known).
// ---------------------------------------------------------------------------
#define PXo  0
#define PWo  (PXo + EE * PROWS)
#define PQo  (PWo + 3 * PCH * 192)
#define PKo  (PQo + DD * PROWS)
#define PROJ_SMEM_FLOATS (PKo + DD * PROWS + 4)
#define PROJ_SMEM_BYTES  (PROJ_SMEM_FLOATS * 4)

__global__ __launch_bounds__(192, 2) void proj_kernel(
    const float* __restrict__ x,
    const float* __restrict__ Wq, const float* __restrict__ bq,
    const float* __restrict__ Wk, const float* __restrict__ bk,
    const float* __restrict__ Wv, const float* __restrict__ bv,
    const float* __restrict__ W1, const float* __restrict__ b1)
{
    extern __shared__ __align__(16) float sm[];
    float* x_sT = sm + PXo;       // [e][row]
    float* w_s  = sm + PWo;       // [3][e][col(192)]
    float* q_sT = sm + PQo;       // [dd][row]
    float* k_sT = sm + PKo;       // [dd][row]

    const int r0 = blockIdx.x * PROWS;
    const int t  = threadIdx.x;

    const float* Wmat[3] = { Wq, Wk, Wv };

#define STAGE_W(e0, buf) do {                                            \
        float* _db = w_s + (buf) * PCH * 192;                            \
        _Pragma("unroll")                                                \
        for (int u = 0; u < 8; u++) {                                    \
            int idx = t + u * 192;                                       \
            int rw = idx / 48, col4 = idx % 48;                          \
            int wch = col4 >> 4, c4 = col4 & 15;                         \
            cp16(&_db[rw * 192 + col4 * 4],                              \
                 Wmat[wch] + (((e0) + rw) * 16 + c4) * 4);               \
        }                                                                \
        cp_commit();                                                     \
    } while (0)

    STAGE_W(0, 0);

    // stage x transposed: x_sT[e][row]
    {
        const float4* x4 = (const float4*)(x + r0 * EE);
        for (int idx = t; idx < PROWS * EE / 4; idx += 192) {
            int row = idx >> 6, e4 = idx & 63;
            float4 v = x4[row * 64 + e4];
            x_sT[(e4 * 4 + 0) * PROWS + row] = v.x;
            x_sT[(e4 * 4 + 1) * PROWS + row] = v.y;
            x_sT[(e4 * 4 + 2) * PROWS + row] = v.z;
            x_sT[(e4 * 4 + 3) * PROWS + row] = v.w;
        }
    }
    STAGE_W(PCH, 1);

    // Phase A map: which[3] x colpair[32] x rowgroup[2] -> 4 rows x 2 cols
    const int which = t >> 6;            // 0..2
    const int cp    = (t >> 1) & 31;     // 0..31 (cols cp*2, cp*2+1)
    const int rg    = (t & 1) * 4;       // rows rg..rg+3

    float2 a[4];
    #pragma unroll
    for (int r = 0; r < 4; r++) a[r] = make_float2(0.f, 0.f);

    for (int c = 0; c < NPCH; c++) {
        cp_wait<1>();
        __syncthreads();

        if (c + 2 < NPCH) {
            STAGE_W((c + 2) * PCH, (c + 2) % 3);
        } else if (c == NPCH - 2) {
            float* dst = w_s + ((c + 2) % 3) * PCH * 192;   // W1 rows 0..95
            #pragma unroll
            for (int u = 0; u < 8; u++) {
                int idx = t + u * 192;
                cp16(&dst[idx * 4], W1 + idx * 4);
            }
            cp_commit();
        } else {
            float* dst = w_s + ((c + 2) % 3) * PCH * 192;   // W1 rows 96..127
            for (int idx = t; idx < 512; idx += 192)
                cp16(&dst[idx * 4], W1 + 6144 + idx * 4);
            cp_commit();
        }

        const float* wb = w_s + (c % 3) * PCH * 192 + which * 64 + cp * 2;
        const float* xb = x_sT + c * PCH * PROWS + rg;
        #pragma unroll
        for (int e = 0; e < PCH; e++) {
            float2 w2v = *(const float2*)(wb + e * 192);
            float4 xv  = *(const float4*)(xb + e * PROWS);
            a[0].x = fmaf(xv.x, w2v.x, a[0].x); a[0].y = fmaf(xv.x, w2v.y, a[0].y);
            a[1].x = fmaf(xv.y, w2v.x, a[1].x); a[1].y = fmaf(xv.y, w2v.y, a[1].y);
            a[2].x = fmaf(xv.z, w2v.x, a[2].x); a[2].y = fmaf(xv.z, w2v.y, a[2].y);
            a[3].x = fmaf(xv.w, w2v.x, a[3].x); a[3].y = fmaf(xv.w, w2v.y, a[3].y);
        }
    }
#undef STAGE_W

    // W1 after loop: rows 0..95 in buf2, rows 96..127 in buf0
    const float* w1a = w_s + 2 * PCH * 192;
    const float* w1b = w_s;

    // Phase A epilogue: bias (+relu), write v / q_sT / k_sT
    {
        const float* bias3 = (which == 0) ? bq : (which == 1 ? bk : bv);
        float2 bias2 = *(const float2*)(bias3 + cp * 2);
        #pragma unroll
        for (int r = 0; r < 4; r++) {
            float2 o;
            o.x = a[r].x + bias2.x;
            o.y = a[r].y + bias2.y;
            if (which == 2) {
                *(float2*)&g_v[(r0 + rg + r) * DD + cp * 2] = o;
            } else {
                float* dst = (which == 0) ? q_sT : k_sT;
                dst[(cp * 2 + 0) * PROWS + rg + r] = fmaxf(o.x, 0.f);
                dst[(cp * 2 + 1) * PROWS + rg + r] = fmaxf(o.y, 0.f);
            }
        }
    }
    cp_wait<0>();
    __syncthreads();

    // Phase B: qp (with b1) and kp; threads 0..127, 4 rows x 2 cols
    if (t < 128) {
        const int sel = t >> 6;            // 0 = qp, 1 = kp
        const int cpb = (t >> 1) & 31;
        const int rb  = (t & 1) * 4;

        float2 b2[4];
        #pragma unroll
        for (int r = 0; r < 4; r++) b2[r] = make_float2(0.f, 0.f);

        if (sel == 0) {
            #pragma unroll 16
            for (int e = 0; e < DD; e++) {
                float2 w2v = *(const float2*)(w1a + e * 64 + cpb * 2);
                float4 xv  = *(const float4*)(q_sT + e * PROWS + rb);
                b2[0].x = fmaf(xv.x, w2v.x, b2[0].x); b2[0].y = fmaf(xv.x, w2v.y, b2[0].y);
                b2[1].x = fmaf(xv.y, w2v.x, b2[1].x); b2[1].y = fmaf(xv.y, w2v.y, b2[1].y);
                b2[2].x = fmaf(xv.z, w2v.x, b2[2].x); b2[2].y = fmaf(xv.z, w2v.y, b2[2].y);
                b2[3].x = fmaf(xv.w, w2v.x, b2[3].x); b2[3].y = fmaf(xv.w, w2v.y, b2[3].y);
            }
            float2 bias2 = *(const float2*)((const float*)b1 + cpb * 2);
            #pragma unroll
            for (int r = 0; r < 4; r++) {
                float2 o;
                o.x = b2[r].x + bias2.x;
                o.y = b2[r].y + bias2.y;
                *(float2*)&g_qpb[(r0 + rb + r) * DD + cpb * 2] = o;
            }
        } else {
            #pragma unroll 16
            for (int e = 0; e < 32; e++) {
                float2 w2v = *(const float2*)(w1a + (64 + e) * 64 + cpb * 2);
                float4 xv  = *(const float4*)(k_sT + e * PROWS + rb);
                b2[0].x = fmaf(xv.x, w2v.x, b2[0].x); b2[0].y = fmaf(xv.x, w2v.y, b2[0].y);
                b2[1].x = fmaf(xv.y, w2v.x, b2[1].x); b2[1].y = fmaf(xv.y, w2v.y, b2[1].y);
                b2[2].x = fmaf(xv.z, w2v.x, b2[2].x); b2[2].y = fmaf(xv.z, w2v.y, b2[2].y);
                b2[3].x = fmaf(xv.w, w2v.x, b2[3].x); b2[3].y = fmaf(xv.w, w2v.y, b2[3].y);
            }
            #pragma unroll 16
            for (int e = 32; e < DD; e++) {
                float2 w2v = *(const float2*)(w1b + (e - 32) * 64 + cpb * 2);
                float4 xv  = *(const float4*)(k_sT + e * PROWS + rb);
                b2[0].x = fmaf(xv.x, w2v.x, b2[0].x); b2[0].y = fmaf(xv.x, w2v.y, b2[0].y);
                b2[1].x = fmaf(xv.y, w2v.x, b2[1].x); b2[1].y = fmaf(xv.y, w2v.y, b2[1].y);
                b2[2].x = fmaf(xv.z, w2v.x, b2[2].x); b2[2].y = fmaf(xv.z, w2v.y, b2[2].y);
                b2[3].x = fmaf(xv.w, w2v.x, b2[3].x); b2[3].y = fmaf(xv.w, w2v.y, b2[3].y);
            }
            const int b  = r0 >> 10;
            const int tb = (r0 & 1023) + rb;
            *(float4*)&g_kpT[(b * DD + cpb * 2 + 0) * TT + tb] =
                make_float4(b2[0].x, b2[1].x, b2[2].x, b2[3].x);
            *(float4*)&g_kpT[(b * DD + cpb * 2 + 1) * TT + tb] =
                make_float4(b2[0].y, b2[1].y, b2[2].y, b2[3].y);
        }
    }
}

// ---------------------------------------------------------------------------
// Kernel 2 (v4 FIXED): split-K attention, R9 structure, v via __ldg from
// global (L1/L2-hot): smem 66KB -> ~35KB -> 6 blocks/SM = 12 warps resident.
// FIX vs R14: STAGE_KP copies the FULL [64][64] chunk (u<16 -> 1024 float4s).
// ---------------------------------------------------------------------------
#define SMEM_FLOATS (2 * DD * JCH + 4 * JCH + 4 * DD + DD + 4)
#define SMEM_BYTES  (SMEM_FLOATS * 4)

__global__ __launch_bounds__(64, 6) void attn_kernel(
    const float* __restrict__ W2)
{
    extern __shared__ __align__(16) float smem[];
    float (*kp_s)[DD][JCH] = (float (*)[DD][JCH])smem;                 // [2][d][j]
    float (*p_s)[JCH]      = (float (*)[JCH])(smem + 2 * DD * JCH);    // [4][j]
    float (*q_s)[DD]       = (float (*)[DD])(smem + 2 * DD * JCH + 4 * JCH);
    float *w2_s            = smem + 2 * DD * JCH + 4 * JCH + 4 * DD;

    const int bid  = (int)blockIdx.x;
    const int quad = ((int)gridDim.x / 2 - 1) - (bid >> 1);
    const int s    = bid & 1;
    const int b    = quad >> 8;
    const int i0   = (quad & 255) * 4;
    const int t    = threadIdx.x;
    const int wid  = t >> 5;
    const int lane = t & 31;
    const int ia   = i0 + wid * 2;
    const int ib   = ia + 1;

    if (t < DD) w2_s[t] = W2[t];
    ((float4*)q_s)[t] = ((const float4*)(g_qpb + (b * TT + i0) * DD))[t];

    const float*  kpT_b = g_kpT + b * DD * TT;
    const float2* v2_b  = (const float2*)(g_v + b * TT * DD);

    const int nch = i0 / JCH + 1;

    // stage kp chunk: [64][64] = 1024 float4s over 64 threads (16 each)
#define STAGE_KP(j0, buf) do {                                           \
        _Pragma("unroll")                                                \
        for (int u = 0; u < 16; u++) {                                   \
            int idx = t + u * 64;                                        \
            int d = idx >> 4, cc = idx & 15;                             \
            cp16(&kp_s[buf][d][cc * 4], kpT_b + d * TT + (j0) + cc * 4); \
        }                                                                \
        cp_commit();                                                     \
    } while (0)

    if (s < nch) STAGE_KP(s * JCH, 0);
    else cp_commit();

    const float NEG_INF = __int_as_float(0xff800000);
    float ma = NEG_INF, la = 0.f, mb = NEG_INF, lb = 0.f;
    float axe = 0.f, aye = 0.f, axo = 0.f, ayo = 0.f;
    float bxe = 0.f, bye = 0.f, bxo = 0.f, byo = 0.f;

    const float4* qa4 = (const float4*)q_s[wid * 2];
    const float4* qb4 = (const float4*)q_s[wid * 2 + 1];
    const float4* w24 = (const float4*)w2_s;

    for (int c = s; c < nch; c += 2) {
        cp_wait<0>();
        __syncthreads();

        if (c + 2 < nch)
            STAGE_KP((c + 2) * JCH, ((c >> 1) + 1) & 1);

        const int j0 = c * JCH;
        const int cb2 = (c >> 1) & 1;
        const float (*kp)[JCH] = kp_s[cb2];

        float a0 = 0.f, a1 = 0.f, a2 = 0.f, a3 = 0.f;
        float b0 = 0.f, b1 = 0.f, b2 = 0.f, b3 = 0.f;
        #pragma unroll
        for (int d4 = 0; d4 < 16; d4++) {
            float4 w4 = w24[d4];
            float4 qa = qa4[d4];
            float4 qb = qb4[d4];
            float2 k0 = *(const float2*)&kp[4 * d4 + 0][2 * lane];
            float2 k1 = *(const float2*)&kp[4 * d4 + 1][2 * lane];
            float2 k2 = *(const float2*)&kp[4 * d4 + 2][2 * lane];
            float2 k3 = *(const float2*)&kp[4 * d4 + 3][2 * lane];
            a0 = fmaf(fmaxf(qa.x + k0.x, 0.f), w4.x, a0);
            a1 = fmaf(fmaxf(qa.x + k0.y, 0.f), w4.x, a1);
            a2 = fmaf(fmaxf(qa.y + k1.x, 0.f), w4.y, a2);
            a3 = fmaf(fmaxf(qa.y + k1.y, 0.f), w4.y, a3);
            a0 = fmaf(fmaxf(qa.z + k2.x, 0.f), w4.z, a0);
            a1 = fmaf(fmaxf(qa.z + k2.y, 0.f), w4.z, a1);
            a2 = fmaf(fmaxf(qa.w + k3.x, 0.f), w4.w, a2);
            a3 = fmaf(fmaxf(qa.w + k3.y, 0.f), w4.w, a3);
            b0 = fmaf(fmaxf(qb.x + k0.x, 0.f), w4.x, b0);
            b1 = fmaf(fmaxf(qb.x + k0.y, 0.f), w4.x, b1);
            b2 = fmaf(fmaxf(qb.y + k1.x, 0.f), w4.y, b2);
            b3 = fmaf(fmaxf(qb.y + k1.y, 0.f), w4.y, b3);
            b0 = fmaf(fmaxf(qb.z + k2.x, 0.f), w4.z, b0);
            b1 = fmaf(fmaxf(qb.z + k2.y, 0.f), w4.z, b1);
            b2 = fmaf(fmaxf(qb.w + k3.x, 0.f), w4.w, b2);
            b3 = fmaf(fmaxf(qb.w + k3.y, 0.f), w4.w, b3);
        }
        const int j = j0 + 2 * lane;
        float s0a = (j     <= ia) ? (a0 + a2) : NEG_INF;
        float s1a = (j + 1 <= ia) ? (a1 + a3) : NEG_INF;
        float s0b = (j     <= ib) ? (b0 + b2) : NEG_INF;
        float s1b = (j + 1 <= ib) ? (b1 + b3) : NEG_INF;

        float nma  = fmaxf(ma, warp_max_f32(fmaxf(s0a, s1a)));
        float nmb  = fmaxf(mb, warp_max_f32(fmaxf(s0b, s1b)));
        float ca   = __expf(ma - nma);
        float cb   = __expf(mb - nmb);
        float p0a  = __expf(s0a - nma), p1a = __expf(s1a - nma);
        float p0b  = __expf(s0b - nmb), p1b = __expf(s1b - nmb);
        la = fmaf(la, ca, p0a + p1a);
        lb = fmaf(lb, cb, p0b + p1b);
        axe *= ca; aye *= ca; axo *= ca; ayo *= ca;
        bxe *= cb; bye *= cb; bxo *= cb; byo *= cb;
        ma = nma; mb = nmb;

        *(float2*)&p_s[wid * 2    ][2 * lane] = make_float2(p0a, p1a);
        *(float2*)&p_s[wid * 2 + 1][2 * lane] = make_float2(p0b, p1b);
        __syncwarp();

        // PV: v straight from global (L1/L2-hot; 12 warps hide latency)
        const float2* vrow = v2_b + j0 * 32 + lane;
        #pragma unroll 8
        for (int jj = 0; jj < JCH; jj += 2) {
            float  pae = p_s[wid * 2][jj];
            float  pao = p_s[wid * 2][jj + 1];
            float  pbe = p_s[wid * 2 + 1][jj];
            float  pbo = p_s[wid * 2 + 1][jj + 1];
            float2 ve = __ldg(&vrow[jj * 32]);
            float2 vo = __ldg(&vrow[(jj + 1) * 32]);
            axe = fmaf(pae, ve.x, axe);
            aye = fmaf(pae, ve.y, aye);
            axo = fmaf(pao, vo.x, axo);
            ayo = fmaf(pao, vo.y, ayo);
            bxe = fmaf(pbe, ve.x, bxe);
            bye = fmaf(pbe, ve.y, bye);
            bxo = fmaf(pbo, vo.x, bxo);
            byo = fmaf(pbo, vo.y, byo);
        }
    }
#undef STAGE_KP

    float lta = la, ltb = lb;
    #pragma unroll
    for (int off = 16; off; off >>= 1) {
        lta += __shfl_xor_sync(0xffffffffu, lta, off);
        ltb += __shfl_xor_sync(0xffffffffu, ltb, off);
    }

    *(float2*)&g_po[s][(b * TT + ia) * DD + 2 * lane] = make_float2(axe + axo, aye + ayo);
    *(float2*)&g_po[s][(b * TT + ib) * DD + 2 * lane] = make_float2(bxe + bxo, bye + byo);
    if (lane == 0) {
        g_pm[s][b * TT + ia] = ma;  g_pl[s][b * TT + ia] = lta;
        g_pm[s][b * TT + ib] = mb;  g_pl[s][b * TT + ib] = ltb;
    }
}

// ---------------------------------------------------------------------------
// Kernel 3: combine the two split-K partials.
// ---------------------------------------------------------------------------
__global__ __launch_bounds__(128) void combine_kernel(float* __restrict__ out)
{
    const int row  = blockIdx.x * 4 + (threadIdx.x >> 5);
    const int lane = threadIdx.x & 31;

    float m0 = g_pm[0][row], l0 = g_pl[0][row];
    float m1 = g_pm[1][row], l1 = g_pl[1][row];
    float M  = fmaxf(m0, m1);
    float c0 = __expf(m0 - M);
    float c1 = __expf(m1 - M);
    float inv = 1.0f / fmaf(l0, c0, l1 * c1);

    float2 o0 = *(const float2*)&g_po[0][row * DD + 2 * lane];
    float2 o1 = *(const float2*)&g_po[1][row * DD + 2 * lane];
    *(float2*)&out[row * DD + 2 * lane] =
        make_float2(fmaf(o0.x, c0, o1.x * c1) * inv,
                    fmaf(o0.y, c0, o1.y * c1) * inv);
}

// ---------------------------------------------------------------------------
extern "C" void kernel_launch(void* const* d_in, const int* in_sizes, int n_in,
                              void* d_out, int out_size)
{
    const float* x  = (const float*)d_in[0];
    const float* Wq = (const float*)d_in[1];
    const float* bq = (const float*)d_in[2];
    const float* Wk = (const float*)d_in[3];
    const float* bk = (const float*)d_in[4];
    const float* Wv = (const float*)d_in[5];
    const float* bv = (const float*)d_in[6];
    const float* W1 = (const float*)d_in[7];
    const float* b1 = (const float*)d_in[8];
    const float* W2 = (const float*)d_in[9];
    // b2 (d_in[10]) is a constant shift on scores: cancels in softmax.

    (void)cudaFuncSetAttribute(proj_kernel,
                               cudaFuncAttributeMaxDynamicSharedMemorySize,
                               PROJ_SMEM_BYTES);
    (void)cudaFuncSetAttribute(attn_kernel,
                               cudaFuncAttributeMaxDynamicSharedMemorySize,
                               SMEM_BYTES);

    proj_kernel<<<BB * TT / PROWS, 192, PROJ_SMEM_BYTES>>>(
        x, Wq, bq, Wk, bk, Wv, bv, W1, b1);
    attn_kernel<<<BB * TT / 4 * 2, 64, SMEM_BYTES>>>(W2);
    combine_kernel<<<BB * TT / 4, 128>>>((float*)d_out);
}

// round 16
// speedup vs baseline: 1.0934x; 1.0934x over previous
#include <cuda_runtime.h>

#define TT 1024
#define EE 256
#define DD 64
#define BB 2
#define JCH 64        // keys per chunk (attn)
#define PROWS 8       // rows per proj block (grid = 256)
#define PCH 32        // e-rows per proj weight chunk
#define NPCH (EE / PCH)

// Scratch (device globals: no allocation allowed in kernel_launch)
__device__ float g_qpb[BB * TT * DD];   // qp + b1, row-major [row][d]
__device__ float g_kpT[BB * DD * TT];   // kp transposed   [b][d][t]
__device__ float g_v  [BB * TT * DD];   // v, row-major    [row][dv]
// split-K partials
__device__ float g_po[2][BB * TT * DD]; // unnormalized o
__device__ float g_pm[2][BB * TT];      // running max
__device__ float g_pl[2][BB * TT];      // denominator

__device__ __forceinline__ void cp16(float* dst, const float* src) {
    unsigned d = (unsigned)__cvta_generic_to_shared(dst);
    asm volatile("cp.async.cg.shared.global [%0], [%1], 16;" :: "r"(d), "l"(src));
}
__device__ __forceinline__ void cp_commit() { asm volatile("cp.async.commit_group;"); }
template <int N>
__device__ __forceinline__ void cp_wait() { asm volatile("cp.async.wait_group %0;" :: "n"(N)); }

// Warp-wide float max via integer redux.sync (f32 redux doesn't exist).
__device__ __forceinline__ float warp_max_f32(float x) {
    unsigned ix = __float_as_uint(x);
    ix = (ix & 0x80000000u) ? ~ix : (ix | 0x80000000u);
    unsigned r = __reduce_max_sync(0xffffffffu, ix);
    r = (r & 0x80000000u) ? (r & 0x7fffffffu) : ~r;
    return __uint_as_float(r);
}

// ---------------------------------------------------------------------------
// Kernel 1 (v4c): projections — unchanged from R13 (best known).
// ---------------------------------------------------------------------------
#define PXo  0
#define PWo  (PXo + EE * PROWS)
#define PQo  (PWo + 3 * PCH * 192)
#define PKo  (PQo + DD * PROWS)
#define PROJ_SMEM_FLOATS (PKo + DD * PROWS + 4)
#define PROJ_SMEM_BYTES  (PROJ_SMEM_FLOATS * 4)

__global__ __launch_bounds__(192, 2) void proj_kernel(
    const float* __restrict__ x,
    const float* __restrict__ Wq, const float* __restrict__ bq,
    const float* __restrict__ Wk, const float* __restrict__ bk,
    const float* __restrict__ Wv, const float* __restrict__ bv,
    const float* __restrict__ W1, const float* __restrict__ b1)
{
    extern __shared__ __align__(16) float sm[];
    float* x_sT = sm + PXo;       // [e][row]
    float* w_s  = sm + PWo;       // [3][e][col(192)]
    float* q_sT = sm + PQo;       // [dd][row]
    float* k_sT = sm + PKo;       // [dd][row]

    const int r0 = blockIdx.x * PROWS;
    const int t  = threadIdx.x;

    const float* Wmat[3] = { Wq, Wk, Wv };

#define STAGE_W(e0, buf) do {                                            \
        float* _db = w_s + (buf) * PCH * 192;                            \
        _Pragma("unroll")                                                \
        for (int u = 0; u < 8; u++) {                                    \
            int idx = t + u * 192;                                       \
            int rw = idx / 48, col4 = idx % 48;                          \
            int wch = col4 >> 4, c4 = col4 & 15;                         \
            cp16(&_db[rw * 192 + col4 * 4],                              \
                 Wmat[wch] + (((e0) + rw) * 16 + c4) * 4);               \
        }                                                                \
        cp_commit();                                                     \
    } while (0)

    STAGE_W(0, 0);

    // stage x transposed: x_sT[e][row]
    {
        const float4* x4 = (const float4*)(x + r0 * EE);
        for (int idx = t; idx < PROWS * EE / 4; idx += 192) {
            int row = idx >> 6, e4 = idx & 63;
            float4 v = x4[row * 64 + e4];
            x_sT[(e4 * 4 + 0) * PROWS + row] = v.x;
            x_sT[(e4 * 4 + 1) * PROWS + row] = v.y;
            x_sT[(e4 * 4 + 2) * PROWS + row] = v.z;
            x_sT[(e4 * 4 + 3) * PROWS + row] = v.w;
        }
    }
    STAGE_W(PCH, 1);

    // Phase A map: which[3] x colpair[32] x rowgroup[2] -> 4 rows x 2 cols
    const int which = t >> 6;            // 0..2
    const int cp    = (t >> 1) & 31;     // 0..31 (cols cp*2, cp*2+1)
    const int rg    = (t & 1) * 4;       // rows rg..rg+3

    float2 a[4];
    #pragma unroll
    for (int r = 0; r < 4; r++) a[r] = make_float2(0.f, 0.f);

    for (int c = 0; c < NPCH; c++) {
        cp_wait<1>();
        __syncthreads();

        if (c + 2 < NPCH) {
            STAGE_W((c + 2) * PCH, (c + 2) % 3);
        } else if (c == NPCH - 2) {
            float* dst = w_s + ((c + 2) % 3) * PCH * 192;   // W1 rows 0..95
            #pragma unroll
            for (int u = 0; u < 8; u++) {
                int idx = t + u * 192;
                cp16(&dst[idx * 4], W1 + idx * 4);
            }
            cp_commit();
        } else {
            float* dst = w_s + ((c + 2) % 3) * PCH * 192;   // W1 rows 96..127
            for (int idx = t; idx < 512; idx += 192)
                cp16(&dst[idx * 4], W1 + 6144 + idx * 4);
            cp_commit();
        }

        const float* wb = w_s + (c % 3) * PCH * 192 + which * 64 + cp * 2;
        const float* xb = x_sT + c * PCH * PROWS + rg;
        #pragma unroll
        for (int e = 0; e < PCH; e++) {
            float2 w2v = *(const float2*)(wb + e * 192);
            float4 xv  = *(const float4*)(xb + e * PROWS);
            a[0].x = fmaf(xv.x, w2v.x, a[0].x); a[0].y = fmaf(xv.x, w2v.y, a[0].y);
            a[1].x = fmaf(xv.y, w2v.x, a[1].x); a[1].y = fmaf(xv.y, w2v.y, a[1].y);
            a[2].x = fmaf(xv.z, w2v.x, a[2].x); a[2].y = fmaf(xv.z, w2v.y, a[2].y);
            a[3].x = fmaf(xv.w, w2v.x, a[3].x); a[3].y = fmaf(xv.w, w2v.y, a[3].y);
        }
    }
#undef STAGE_W

    // W1 after loop: rows 0..95 in buf2, rows 96..127 in buf0
    const float* w1a = w_s + 2 * PCH * 192;
    const float* w1b = w_s;

    // Phase A epilogue: bias (+relu), write v / q_sT / k_sT
    {
        const float* bias3 = (which == 0) ? bq : (which == 1 ? bk : bv);
        float2 bias2 = *(const float2*)(bias3 + cp * 2);
        #pragma unroll
        for (int r = 0; r < 4; r++) {
            float2 o;
            o.x = a[r].x + bias2.x;
            o.y = a[r].y + bias2.y;
            if (which == 2) {
                *(float2*)&g_v[(r0 + rg + r) * DD + cp * 2] = o;
            } else {
                float* dst = (which == 0) ? q_sT : k_sT;
                dst[(cp * 2 + 0) * PROWS + rg + r] = fmaxf(o.x, 0.f);
                dst[(cp * 2 + 1) * PROWS + rg + r] = fmaxf(o.y, 0.f);
            }
        }
    }
    cp_wait<0>();
    __syncthreads();

    // Phase B: qp (with b1) and kp; threads 0..127, 4 rows x 2 cols
    if (t < 128) {
        const int sel = t >> 6;            // 0 = qp, 1 = kp
        const int cpb = (t >> 1) & 31;
        const int rb  = (t & 1) * 4;

        float2 b2[4];
        #pragma unroll
        for (int r = 0; r < 4; r++) b2[r] = make_float2(0.f, 0.f);

        if (sel == 0) {
            #pragma unroll 16
            for (int e = 0; e < DD; e++) {
                float2 w2v = *(const float2*)(w1a + e * 64 + cpb * 2);
                float4 xv  = *(const float4*)(q_sT + e * PROWS + rb);
                b2[0].x = fmaf(xv.x, w2v.x, b2[0].x); b2[0].y = fmaf(xv.x, w2v.y, b2[0].y);
                b2[1].x = fmaf(xv.y, w2v.x, b2[1].x); b2[1].y = fmaf(xv.y, w2v.y, b2[1].y);
                b2[2].x = fmaf(xv.z, w2v.x, b2[2].x); b2[2].y = fmaf(xv.z, w2v.y, b2[2].y);
                b2[3].x = fmaf(xv.w, w2v.x, b2[3].x); b2[3].y = fmaf(xv.w, w2v.y, b2[3].y);
            }
            float2 bias2 = *(const float2*)((const float*)b1 + cpb * 2);
            #pragma unroll
            for (int r = 0; r < 4; r++) {
                float2 o;
                o.x = b2[r].x + bias2.x;
                o.y = b2[r].y + bias2.y;
                *(float2*)&g_qpb[(r0 + rb + r) * DD + cpb * 2] = o;
            }
        } else {
            #pragma unroll 16
            for (int e = 0; e < 32; e++) {
                float2 w2v = *(const float2*)(w1a + (64 + e) * 64 + cpb * 2);
                float4 xv  = *(const float4*)(k_sT + e * PROWS + rb);
                b2[0].x = fmaf(xv.x, w2v.x, b2[0].x); b2[0].y = fmaf(xv.x, w2v.y, b2[0].y);
                b2[1].x = fmaf(xv.y, w2v.x, b2[1].x); b2[1].y = fmaf(xv.y, w2v.y, b2[1].y);
                b2[2].x = fmaf(xv.z, w2v.x, b2[2].x); b2[2].y = fmaf(xv.z, w2v.y, b2[2].y);
                b2[3].x = fmaf(xv.w, w2v.x, b2[3].x); b2[3].y = fmaf(xv.w, w2v.y, b2[3].y);
            }
            #pragma unroll 16
            for (int e = 32; e < DD; e++) {
                float2 w2v = *(const float2*)(w1b + (e - 32) * 64 + cpb * 2);
                float4 xv  = *(const float4*)(k_sT + e * PROWS + rb);
                b2[0].x = fmaf(xv.x, w2v.x, b2[0].x); b2[0].y = fmaf(xv.x, w2v.y, b2[0].y);
                b2[1].x = fmaf(xv.y, w2v.x, b2[1].x); b2[1].y = fmaf(xv.y, w2v.y, b2[1].y);
                b2[2].x = fmaf(xv.z, w2v.x, b2[2].x); b2[2].y = fmaf(xv.z, w2v.y, b2[2].y);
                b2[3].x = fmaf(xv.w, w2v.x, b2[3].x); b2[3].y = fmaf(xv.w, w2v.y, b2[3].y);
            }
            const int b  = r0 >> 10;
            const int tb = (r0 & 1023) + rb;
            *(float4*)&g_kpT[(b * DD + cpb * 2 + 0) * TT + tb] =
                make_float4(b2[0].x, b2[1].x, b2[2].x, b2[3].x);
            *(float4*)&g_kpT[(b * DD + cpb * 2 + 1) * TT + tb] =
                make_float4(b2[0].y, b2[1].y, b2[2].y, b2[3].y);
        }
    }
}

// ---------------------------------------------------------------------------
// Kernel 2 (v5): split-K attention, smem v (R13 inner loop, proven),
// but 8 queries/block (4 warps, 128 thr): the 66KB kp+v buffers serve
// 2x the queries -> 12 resident warps/SM (was 6), staging traffic /2.
// ---------------------------------------------------------------------------
#define SMEM_FLOATS (2 * DD * JCH + 2 * JCH * DD + 8 * JCH + 8 * DD + DD + 4)
#define SMEM_BYTES  (SMEM_FLOATS * 4)

__global__ __launch_bounds__(128, 3) void attn_kernel(
    const float* __restrict__ W2)
{
    extern __shared__ __align__(16) float smem[];
    float (*kp_s)[DD][JCH] = (float (*)[DD][JCH])smem;                  // [2][d][j]
    float (*v_s)[JCH][DD]  = (float (*)[JCH][DD])(smem + 2 * DD * JCH); // [2][j][dv]
    float (*p_s)[JCH]      = (float (*)[JCH])(smem + 4 * DD * JCH);     // [8][j]
    float (*q_s)[DD]       = (float (*)[DD])(smem + 4 * DD * JCH + 8 * JCH); // [8][d]
    float *w2_s            = smem + 4 * DD * JCH + 8 * JCH + 8 * DD;

    const int bid  = (int)blockIdx.x;
    const int oct  = ((int)gridDim.x / 2 - 1) - (bid >> 1);   // heavy-first
    const int s    = bid & 1;                                  // split id
    const int b    = oct >> 7;                                 // 128 octs/batch
    const int i0   = (oct & 127) * 8;
    const int t    = threadIdx.x;
    const int wid  = t >> 5;
    const int lane = t & 31;
    const int ia   = i0 + wid * 2;       // this warp's two query rows
    const int ib   = ia + 1;

    if (t < DD) w2_s[t] = W2[t];
    // stage 8 query rows (128 float4s over 128 threads)
    ((float4*)q_s)[t] = ((const float4*)(g_qpb + (b * TT + i0) * DD))[t];

    const float* kpT_b = g_kpT + b * DD * TT;
    const float* v_b   = g_v   + b * TT * DD;

    const int nch = i0 / JCH + 1;        // covers keys <= i0+7 (i0 mult of 8)

    // stage chunk: kp 1024 f4 + v 1024 f4 over 128 threads (8 each per array)
#define STAGE_CHUNK(j0, buf) do {                                        \
        _Pragma("unroll")                                                \
        for (int u = 0; u < 8; u++) {                                    \
            int idx = t + u * 128;                                       \
            int d = idx >> 4, cc = idx & 15;                             \
            cp16(&kp_s[buf][d][cc * 4], kpT_b + d * TT + (j0) + cc * 4); \
            cp16(&v_s[buf][0][0] + idx * 4, v_b + (j0) * DD + idx * 4);  \
        }                                                                \
        cp_commit();                                                     \
    } while (0)

    if (s < nch) STAGE_CHUNK(s * JCH, 0);
    else cp_commit();

    const float NEG_INF = __int_as_float(0xff800000);
    float ma = NEG_INF, la = 0.f, mb = NEG_INF, lb = 0.f;
    float axe = 0.f, aye = 0.f, axo = 0.f, ayo = 0.f;
    float bxe = 0.f, bye = 0.f, bxo = 0.f, byo = 0.f;

    const float4* qa4 = (const float4*)q_s[wid * 2];
    const float4* qb4 = (const float4*)q_s[wid * 2 + 1];
    const float4* w24 = (const float4*)w2_s;

    for (int c = s; c < nch; c += 2) {
        cp_wait<0>();
        __syncthreads();                  // chunk c staged & visible

        if (c + 2 < nch)
            STAGE_CHUNK((c + 2) * JCH, ((c >> 1) + 1) & 1);

        const int j0 = c * JCH;
        const int cb2 = (c >> 1) & 1;
        const float (*kp)[JCH] = kp_s[cb2];
        const float (*vv_s)[DD] = v_s[cb2];

        float a0 = 0.f, a1 = 0.f, a2 = 0.f, a3 = 0.f;
        float b0 = 0.f, b1 = 0.f, b2 = 0.f, b3 = 0.f;
        #pragma unroll
        for (int d4 = 0; d4 < 16; d4++) {
            float4 w4 = w24[d4];
            float4 qa = qa4[d4];
            float4 qb = qb4[d4];
            float2 k0 = *(const float2*)&kp[4 * d4 + 0][2 * lane];
            float2 k1 = *(const float2*)&kp[4 * d4 + 1][2 * lane];
            float2 k2 = *(const float2*)&kp[4 * d4 + 2][2 * lane];
            float2 k3 = *(const float2*)&kp[4 * d4 + 3][2 * lane];
            a0 = fmaf(fmaxf(qa.x + k0.x, 0.f), w4.x, a0);
            a1 = fmaf(fmaxf(qa.x + k0.y, 0.f), w4.x, a1);
            a2 = fmaf(fmaxf(qa.y + k1.x, 0.f), w4.y, a2);
            a3 = fmaf(fmaxf(qa.y + k1.y, 0.f), w4.y, a3);
            a0 = fmaf(fmaxf(qa.z + k2.x, 0.f), w4.z, a0);
            a1 = fmaf(fmaxf(qa.z + k2.y, 0.f), w4.z, a1);
            a2 = fmaf(fmaxf(qa.w + k3.x, 0.f), w4.w, a2);
            a3 = fmaf(fmaxf(qa.w + k3.y, 0.f), w4.w, a3);
            b0 = fmaf(fmaxf(qb.x + k0.x, 0.f), w4.x, b0);
            b1 = fmaf(fmaxf(qb.x + k0.y, 0.f), w4.x, b1);
            b2 = fmaf(fmaxf(qb.y + k1.x, 0.f), w4.y, b2);
            b3 = fmaf(fmaxf(qb.y + k1.y, 0.f), w4.y, b3);
            b0 = fmaf(fmaxf(qb.z + k2.x, 0.f), w4.z, b0);
            b1 = fmaf(fmaxf(qb.z + k2.y, 0.f), w4.z, b1);
            b2 = fmaf(fmaxf(qb.w + k3.x, 0.f), w4.w, b2);
            b3 = fmaf(fmaxf(qb.w + k3.y, 0.f), w4.w, b3);
        }
        const int j = j0 + 2 * lane;
        float s0a = (j     <= ia) ? (a0 + a2) : NEG_INF;
        float s1a = (j + 1 <= ia) ? (a1 + a3) : NEG_INF;
        float s0b = (j     <= ib) ? (b0 + b2) : NEG_INF;
        float s1b = (j + 1 <= ib) ? (b1 + b3) : NEG_INF;

        float nma  = fmaxf(ma, warp_max_f32(fmaxf(s0a, s1a)));
        float nmb  = fmaxf(mb, warp_max_f32(fmaxf(s0b, s1b)));
        float ca   = __expf(ma - nma);
        float cb   = __expf(mb - nmb);
        float p0a  = __expf(s0a - nma), p1a = __expf(s1a - nma);
        float p0b  = __expf(s0b - nmb), p1b = __expf(s1b - nmb);
        la = fmaf(la, ca, p0a + p1a);
        lb = fmaf(lb, cb, p0b + p1b);
        axe *= ca; aye *= ca; axo *= ca; ayo *= ca;
        bxe *= cb; bye *= cb; bxo *= cb; byo *= cb;
        ma = nma; mb = nmb;

        *(float2*)&p_s[wid * 2    ][2 * lane] = make_float2(p0a, p1a);
        *(float2*)&p_s[wid * 2 + 1][2 * lane] = make_float2(p0b, p1b);
        __syncwarp();

        #pragma unroll
        for (int jj = 0; jj < JCH; jj += 2) {
            float  pae = p_s[wid * 2][jj];
            float  pao = p_s[wid * 2][jj + 1];
            float  pbe = p_s[wid * 2 + 1][jj];
            float  pbo = p_s[wid * 2 + 1][jj + 1];
            float2 ve = *(const float2*)&vv_s[jj][2 * lane];
            float2 vo = *(const float2*)&vv_s[jj + 1][2 * lane];
            axe = fmaf(pae, ve.x, axe);
            aye = fmaf(pae, ve.y, aye);
            axo = fmaf(pao, vo.x, axo);
            ayo = fmaf(pao, vo.y, ayo);
            bxe = fmaf(pbe, ve.x, bxe);
            bye = fmaf(pbe, ve.y, bye);
            bxo = fmaf(pbo, vo.x, bxo);
            byo = fmaf(pbo, vo.y, byo);
        }
    }
#undef STAGE_CHUNK

    float lta = la, ltb = lb;
    #pragma unroll
    for (int off = 16; off; off >>= 1) {
        lta += __shfl_xor_sync(0xffffffffu, lta, off);
        ltb += __shfl_xor_sync(0xffffffffu, ltb, off);
    }

    *(float2*)&g_po[s][(b * TT + ia) * DD + 2 * lane] = make_float2(axe + axo, aye + ayo);
    *(float2*)&g_po[s][(b * TT + ib) * DD + 2 * lane] = make_float2(bxe + bxo, bye + byo);
    if (lane == 0) {
        g_pm[s][b * TT + ia] = ma;  g_pl[s][b * TT + ia] = lta;
        g_pm[s][b * TT + ib] = mb;  g_pl[s][b * TT + ib] = ltb;
    }
}

// ---------------------------------------------------------------------------
// Kernel 3: combine the two split-K partials.
// ---------------------------------------------------------------------------
__global__ __launch_bounds__(128) void combine_kernel(float* __restrict__ out)
{
    const int row  = blockIdx.x * 4 + (threadIdx.x >> 5);
    const int lane = threadIdx.x & 31;

    float m0 = g_pm[0][row], l0 = g_pl[0][row];
    float m1 = g_pm[1][row], l1 = g_pl[1][row];
    float M  = fmaxf(m0, m1);
    float c0 = __expf(m0 - M);
    float c1 = __expf(m1 - M);
    float inv = 1.0f / fmaf(l0, c0, l1 * c1);

    float2 o0 = *(const float2*)&g_po[0][row * DD + 2 * lane];
    float2 o1 = *(const float2*)&g_po[1][row * DD + 2 * lane];
    *(float2*)&out[row * DD + 2 * lane] =
        make_float2(fmaf(o0.x, c0, o1.x * c1) * inv,
                    fmaf(o0.y, c0, o1.y * c1) * inv);
}

// ---------------------------------------------------------------------------
extern "C" void kernel_launch(void* const* d_in, const int* in_sizes, int n_in,
                              void* d_out, int out_size)
{
    const float* x  = (const float*)d_in[0];
    const float* Wq = (const float*)d_in[1];
    const float* bq = (const float*)d_in[2];
    const float* Wk = (const float*)d_in[3];
    const float* bk = (const float*)d_in[4];
    const float* Wv = (const float*)d_in[5];
    const float* bv = (const float*)d_in[6];
    const float* W1 = (const float*)d_in[7];
    const float* b1 = (const float*)d_in[8];
    const float* W2 = (const float*)d_in[9];
    // b2 (d_in[10]) is a constant shift on scores: cancels in softmax.

    (void)cudaFuncSetAttribute(proj_kernel,
                               cudaFuncAttributeMaxDynamicSharedMemorySize,
                               PROJ_SMEM_BYTES);
    (void)cudaFuncSetAttribute(attn_kernel,
                               cudaFuncAttributeMaxDynamicSharedMemorySize,
                               SMEM_BYTES);

    proj_kernel<<<BB * TT / PROWS, 192, PROJ_SMEM_BYTES>>>(
        x, Wq, bq, Wk, bk, Wv, bv, W1, b1);
    attn_kernel<<<BB * TT / 8 * 2, 128, SMEM_BYTES>>>(W2);
    combine_kernel<<<BB * TT / 4, 128>>>((float*)d_out);
}